// round 12
// baseline (speedup 1.0000x reference)
#include <cuda_runtime.h>
#include <cuda_bf16.h>

#define NP 8192
#define GD 48                      // cells per dimension (cell = 0.2 = 2h)
#define GD2 (GD * GD)
#define NCELLS (GD * GD * GD)      // 110592
#define CAP 20                     // slots per cell (Poisson(~4.2) -> P(>20) ~ 1e-9)
#define CELL_INV 5.0f              // 1 / 0.2
#define GMIN 4.8f                  // grid covers [-4.8, 4.8); outliers clamp (safe)
#define INV_H 10.0f
#define EPS 1e-10f

#define NBLK 256
#define NTHR 256                   // NBLK*NTHR = NP*8
#define NSUB 8                     // arrival sub-counters
#define SUBSZ (NBLK / NSUB)        // 32 arrivals per sub-counter

// 8 / (PI * H^3) — matches reference constant
__device__ __constant__ float kNorm = (float)(8.0 / (3.14159265 * 0.001));

// Invariants at entry of every call (input identical every call):
//  - d_cnt all-zero (first call: .bss; later: phase A zeroed the touched set
//    recorded in d_pcell by the previous call's phase B).
//  - sub_cnt[], root_cnt == 0 (self-reset before release).
//  - rel_flag == 0 (toggles twice per call).
__device__ int      d_cnt[NCELLS];
__device__ float4   d_slot[NCELLS * CAP];
__device__ int      d_pcell[NP];
__device__ unsigned sub_cnt[NSUB];
__device__ unsigned root_cnt;
__device__ unsigned rel_flag;

__device__ __forceinline__ int cell_coord(float v) {
    int c = __float2int_rd((v + GMIN) * CELL_INV);
    return min(max(c, 0), GD - 1);
}

// Base cell of the 2-cell-per-axis support window; in [0, GD-2].
__device__ __forceinline__ int cell_base(float v) {
    float u  = (v + GMIN) * CELL_INV;
    int   ix = __float2int_rd(u);
    int   b  = ix + ((u - (float)ix < 0.5f) ? -1 : 0);
    return min(max(b, 0), GD - 2);
}

// Hierarchical sense-reversing grid barrier.
// Arrivals: 32 per sub-counter (8 counters in parallel), then 8 at root.
// Release: single flag, spin-read (L2 broadcast). All counters self-reset.
__device__ __forceinline__ void grid_barrier(unsigned& sense) {
    __syncthreads();
    if (threadIdx.x == 0) {
        sense ^= 1u;
        __threadfence();                              // publish phase writes
        unsigned g = blockIdx.x & (NSUB - 1);
        if (atomicAdd(&sub_cnt[g], 1u) == SUBSZ - 1) {
            sub_cnt[g] = 0u;                          // reset before release
            __threadfence();
            if (atomicAdd(&root_cnt, 1u) == NSUB - 1) {
                root_cnt = 0u;
                __threadfence();
                *(volatile unsigned*)&rel_flag = sense;   // release
            } else {
                while (*(volatile unsigned*)&rel_flag != sense) { }
            }
        } else {
            while (*(volatile unsigned*)&rel_flag != sense) { }
        }
        __threadfence();                              // acquire
    }
    __syncthreads();
}

__global__ void __launch_bounds__(NTHR) fused_kernel(
    const float* __restrict__ pos, float* __restrict__ out)
{
    unsigned sense = 0u;
    const int t = blockIdx.x * NTHR + threadIdx.x;    // 0 .. NP*8-1
    const int i = t >> 3;
    const int s = t & 7;

    // Issue all cold loads up front (overlap with launch ramp).
    const int   pc = d_pcell[i];
    const float xi = pos[3 * i + 0];
    const float yi = pos[3 * i + 1];
    const float zi = pos[3 * i + 2];

    // ---- Phase A: zero previous call's touched cells ----
    if (s == 0) d_cnt[pc] = 0;                        // racing identical stores: benign

    grid_barrier(sense);

    // ---- Phase B: build ----
    if (s == 0) {
        int c = (cell_coord(zi) * GD + cell_coord(yi)) * GD + cell_coord(xi);
        int slot = atomicAdd(&d_cnt[c], 1);
        if (slot < CAP) d_slot[c * CAP + slot] = make_float4(xi, yi, zi, 0.0f);
        if (c != pc) d_pcell[i] = c;                  // only first call stores
    }

    grid_barrier(sense);

    // ---- Phase C: query (8 lanes per particle, one cell each) ----
    const int cx = cell_base(xi) + (s & 1);
    const int cy = cell_base(yi) + ((s >> 1) & 1);
    const int cz = cell_base(zi) + (s >> 2);
    const int c  = (cz * GD + cy) * GD + cx;

    float acc = 0.0f;
    int n = min(__ldcg(&d_cnt[c]), CAP);              // L1-bypass: cross-SM data
    const float4* sp = &d_slot[c * CAP];
    for (int e = 0; e < n; e++) {
        float4 p = __ldcg(&sp[e]);
        float ddx = p.x - xi;
        float ddy = p.y - yi;
        float ddz = p.z - zi;
        float r2 = fmaf(ddx, ddx, fmaf(ddy, ddy, fmaf(ddz, ddz, EPS)));
        float r;
        asm("sqrt.approx.f32 %0, %1;" : "=f"(r) : "f"(r2));
        float q   = r * INV_H;
        float qm1 = q - 1.0f;
        float wi  = fmaf(q * q * 6.0f, qm1, 1.0f);    // 1 - 6q^2 + 6q^3
        float wo  = -2.0f * qm1 * qm1 * qm1;          // 2(1-q)^3
        float w   = (q <= 0.5f) ? wi : wo;
        acc += (q <= 1.0f) ? w : 0.0f;
    }

    // reduce the 8-lane group (same warp, contiguous lanes)
    acc += __shfl_xor_sync(0xFFFFFFFFu, acc, 1);
    acc += __shfl_xor_sync(0xFFFFFFFFu, acc, 2);
    acc += __shfl_xor_sync(0xFFFFFFFFu, acc, 4);

    if (s == 0) out[i] = acc * kNorm;
}

extern "C" void kernel_launch(void* const* d_in, const int* in_sizes, int n_in,
                              void* d_out, int out_size)
{
    const float* pos = (const float*)d_in[0];
    float* out = (float*)d_out;
    (void)in_sizes; (void)n_in; (void)out_size;

    fused_kernel<<<NBLK, NTHR>>>(pos, out);
}